// round 5
// baseline (speedup 1.0000x reference)
#include <cuda_runtime.h>
#include <cuda_bf16.h>
#include <math.h>
#include <stdint.h>

#define NB 1024
#define ND 64
#define NH 512

typedef __nv_bfloat16 bf16;

// ---------------- fp32 scratch ----------------
__device__ __align__(256) float g_W1T[NH*ND];   // W1T[k,i] = W1[i,k] (x-rows)
__device__ __align__(256) float g_w3s[NH];
__device__ __align__(256) float g_q  [NH];      // q[n] = b3 . W3[n,:]
__device__ __align__(256) float g_h1 [NB*NH];
__device__ __align__(256) float g_h2 [NB*NH];
__device__ __align__(256) float g_U  [NB*NH];
__device__ __align__(256) float g_V  [NB*NH];
__device__ __align__(256) float g_r1 [NB*NH];   // h2raw -> later qw
__device__ __align__(256) float g_r2 [NB*NH];   // z2
__device__ __align__(256) float g_st [NB];
__device__ __align__(256) float g_Gp1[NB*ND];
__device__ __align__(256) float g_Gp2[NB*ND];

// ---------------- bf16 hi/lo split scratch ----------------
__device__ __align__(256) bf16 g_W1Ts_h[NH*ND], g_W1Ts_l[NH*ND];   // [n,k<64] = W1[k,n]
__device__ __align__(256) bf16 g_W3s_h [NH*ND], g_W3s_l [NH*ND];   // [n,j]    = W3[n,j]
__device__ __align__(256) bf16 g_W2Ts_h[NH*NH], g_W2Ts_l[NH*NH];   // [n,k] = W2[k,n]
__device__ __align__(256) bf16 g_W2s_h [NH*NH], g_W2s_l [NH*NH];   // [n,k] = W2[n,k]
__device__ __align__(256) bf16 g_As_h  [NH*NH], g_As_l  [NH*NH];   // [n,k] = A[n,k]
__device__ __align__(256) bf16 g_ATs_h [NH*NH], g_ATs_l [NH*NH];   // [n,k] = A[k,n]
__device__ __align__(256) bf16 g_M2s_h [NH*NH], g_M2s_l [NH*NH];   // [n,k] = 2*(W3 W3^T)[n,k]
__device__ __align__(256) bf16 g_h1s_h [NB*NH], g_h1s_l [NB*NH];
__device__ __align__(256) bf16 g_a1s_h [NB*NH], g_a1s_l [NB*NH];
__device__ __align__(256) bf16 g_d1s_h [NB*NH], g_d1s_l [NB*NH];
__device__ __align__(256) bf16 g_h2s_h [NB*NH], g_h2s_l [NB*NH];
__device__ __align__(256) bf16 g_a2s_h [NB*NH], g_a2s_l [NB*NH];
__device__ __align__(256) bf16 g_wbs_h [NB*NH], g_wbs_l [NB*NH];

// ---------------- helpers ----------------
__device__ __forceinline__ uint32_t smem_u32(const void* p) {
    return (uint32_t)__cvta_generic_to_shared(p);
}
__device__ __forceinline__ void sts_v2(uint32_t addr, uint32_t a, uint32_t b) {
    asm volatile("st.shared.v2.b32 [%0], {%1,%2};" :: "r"(addr), "r"(a), "r"(b));
}
__device__ __forceinline__ void sts128(uint32_t addr, uint4 v) {
    asm volatile("st.shared.v4.b32 [%0], {%1,%2,%3,%4};"
                 :: "r"(addr), "r"(v.x), "r"(v.y), "r"(v.z), "r"(v.w));
}
__device__ __forceinline__ void split2(float x0, float x1, uint32_t& hi, uint32_t& lo) {
    bf16 h0 = __float2bfloat16(x0), h1 = __float2bfloat16(x1);
    bf16 l0 = __float2bfloat16(x0 - __bfloat162float(h0));
    bf16 l1 = __float2bfloat16(x1 - __bfloat162float(h1));
    __nv_bfloat162 H; H.x = h0; H.y = h1;
    __nv_bfloat162 L; L.x = l0; L.y = l1;
    hi = *reinterpret_cast<uint32_t*>(&H);
    lo = *reinterpret_cast<uint32_t*>(&L);
}
__device__ __forceinline__ void splitf(float v, bf16* H, bf16* L, size_t idx) {
    bf16 h = __float2bfloat16(v);
    H[idx] = h;
    L[idx] = __float2bfloat16(v - __bfloat162float(h));
}
__device__ __forceinline__ void store_split(bf16* H, bf16* L, size_t idx,
                                            float v0, float v1) {
    uint32_t hi, lo; split2(v0, v1, hi, lo);
    *reinterpret_cast<uint32_t*>(H + idx) = hi;
    *reinterpret_cast<uint32_t*>(L + idx) = lo;
}
__device__ __forceinline__ void ldsm_x4(uint32_t* r, uint32_t addr) {
    asm volatile("ldmatrix.sync.aligned.m8n8.x4.shared.b16 {%0,%1,%2,%3}, [%4];"
                 : "=r"(r[0]), "=r"(r[1]), "=r"(r[2]), "=r"(r[3]) : "r"(addr));
}
__device__ __forceinline__ void ldsm_x2(uint32_t* r, uint32_t addr) {
    asm volatile("ldmatrix.sync.aligned.m8n8.x2.shared.b16 {%0,%1}, [%2];"
                 : "=r"(r[0]), "=r"(r[1]) : "r"(addr));
}
__device__ __forceinline__ void mma16816(float* c, const uint32_t* a, const uint32_t* b) {
    asm volatile(
        "mma.sync.aligned.m16n8k16.row.col.f32.bf16.bf16.f32 "
        "{%0,%1,%2,%3}, {%4,%5,%6,%7}, {%8,%9}, {%0,%1,%2,%3};"
        : "+f"(c[0]), "+f"(c[1]), "+f"(c[2]), "+f"(c[3])
        : "r"(a[0]), "r"(a[1]), "r"(a[2]), "r"(a[3]), "r"(b[0]), "r"(b[1]));
}
__device__ __forceinline__ uint32_t sw128(uint32_t byte) {
    return byte ^ ((byte >> 3) & 0x70);
}

// ---------------- prep: all weight-derived matrices + splits -----------------
__global__ void prep_kernel(const float* __restrict__ W1,
                            const float* __restrict__ W2,
                            const float* __restrict__ W3,
                            const float* __restrict__ b3) {
    int k = blockIdx.x * 16 + threadIdx.x;
    int l = blockIdx.y * 16 + threadIdx.y;
    float c = 0.f, mv = 0.f;
#pragma unroll
    for (int i = 0; i < ND; i++) {
        c  += W3[l*ND + i] * W1[i*NH + k];
        mv += W3[k*ND + i] * W3[l*ND + i];
    }
    float w2 = W2[k*NH + l];
    float a  = w2 * c;
    splitf(a,        g_As_h,   g_As_l,   (size_t)k*NH + l);
    splitf(a,        g_ATs_h,  g_ATs_l,  (size_t)l*NH + k);
    splitf(w2,       g_W2Ts_h, g_W2Ts_l, (size_t)l*NH + k);
    splitf(w2,       g_W2s_h,  g_W2s_l,  (size_t)k*NH + l);
    splitf(2.f * mv, g_M2s_h,  g_M2s_l,  (size_t)k*NH + l);
    if (k < ND) {
        splitf(W1[k*NH + l], g_W1Ts_h, g_W1Ts_l, (size_t)l*ND + k);
        splitf(W3[l*ND + k], g_W3s_h,  g_W3s_l,  (size_t)l*ND + k);
    }
    if (l < ND) g_W1T[k*ND + l] = W1[l*NH + k];
    if (k == 0 && blockIdx.x == 0) {
        float s1 = 0.f, s2 = 0.f;
#pragma unroll
        for (int j = 0; j < ND; j++) {
            s1 += W3[l*ND + j];
            s2 += b3[j] * W3[l*ND + j];
        }
        g_w3s[l] = s1;
        g_q[l]   = s2;
    }
}

// ---------------- tensor GEMMs ----------------
enum { TM_L1 = 0, TM_H2 = 1, TM_VU = 2, TM_P = 3, TM_QW = 4 };

template<int TMODE, int BM>
__global__ void __launch_bounds__(256, 1)
tmma(const float* __restrict__ pX, const float* __restrict__ pC,
     const float* __restrict__ pT, const float* __restrict__ w1row) {
    extern __shared__ __align__(1024) char tsm[];
    const uint32_t sb = smem_u32(tsm);
    constexpr int XSZ = BM * 128;
    constexpr uint32_t OFF_XH = 0, OFF_XL = XSZ;
    constexpr uint32_t OFF_BH = 2 * XSZ, OFF_BL = 2 * XSZ + 8192;
    constexpr int NT = (BM == 128) ? 4 : 2;
    constexpr int NCHUNK = (TMODE == TM_L1) ? 1 : (TMODE == TM_P) ? 9 : 8;

    const int tid  = threadIdx.x;
    const int lane = tid & 31, wid = tid >> 5;
    const int zm = blockIdx.z;
    const int n0 = blockIdx.x * 64;
    const int m0 = blockIdx.y * BM;
    const int wm = (BM == 128 ? (wid & 3) : (wid & 1)) * 32;
    const int wn = (BM == 128 ? (wid >> 2) * 32 : (wid >> 1) * 16);

    float acc[2][NT][4];
#pragma unroll
    for (int mt = 0; mt < 2; mt++)
#pragma unroll
        for (int nt = 0; nt < NT; nt++)
#pragma unroll
            for (int i = 0; i < 4; i++) acc[mt][nt][i] = 0.f;

    for (int ch = 0; ch < NCHUNK; ch++) {
        const int k0 = ch * 64;
        const bool x_inline = (TMODE == TM_L1) || (TMODE == TM_P && ch == 8);

        // ---- X tile ----
        if (x_inline) {
            // fp32 x [*,64], inline hi/lo split (BM==64 paths only)
            const int row   = tid >> 2;
            const int cbase = (tid & 3) * 16;
            const float* xr = pX + (size_t)(m0 + row) * 64;
#pragma unroll
            for (int i = 0; i < 4; i++) {
                const int col = cbase + i * 4;
                float4 v = *(const float4*)(xr + col);
                uint32_t h01, l01, h23, l23;
                split2(v.x, v.y, h01, l01);
                split2(v.z, v.w, h23, l23);
                uint32_t sw = sw128(row * 128 + col * 2);
                sts_v2(sb + OFF_XH + sw, h01, h23);
                sts_v2(sb + OFF_XL + sw, l01, l23);
            }
        } else {
            const bf16* Xh =
                (TMODE == TM_H2) ? (zm ? g_d1s_h : g_h1s_h) :
                (TMODE == TM_VU) ? (zm ? g_a2s_h : g_a1s_h) :
                (TMODE == TM_P)  ? g_h2s_h : g_wbs_h;
            const bf16* Xl =
                (TMODE == TM_H2) ? (zm ? g_d1s_l : g_h1s_l) :
                (TMODE == TM_VU) ? (zm ? g_a2s_l : g_a1s_l) :
                (TMODE == TM_P)  ? g_h2s_l : g_wbs_l;
            const int row   = (BM == 128) ? (tid >> 1) : (tid >> 2);
            const int cbase = (BM == 128) ? ((tid & 1) * 32) : ((tid & 3) * 16);
            constexpr int NI = (BM == 128) ? 4 : 2;
            const size_t base = (size_t)(m0 + row) * NH + k0;
#pragma unroll
            for (int i = 0; i < NI; i++) {
                const int c = cbase + i * 8;
                uint4 vh = *(const uint4*)(Xh + base + c);
                uint4 vl = *(const uint4*)(Xl + base + c);
                uint32_t sw = sw128(row * 128 + c * 2);
                sts128(sb + OFF_XH + sw, vh);
                sts128(sb + OFF_XL + sw, vl);
            }
        }
        // ---- B tile (always pre-split bf16) ----
        {
            const bf16 *Bh, *Bl;
            int ldb = NH, kb = k0;
            if constexpr (TMODE == TM_L1) { Bh = g_W1Ts_h; Bl = g_W1Ts_l; ldb = ND; kb = 0; }
            else if constexpr (TMODE == TM_H2) { Bh = g_W2Ts_h; Bl = g_W2Ts_l; }
            else if constexpr (TMODE == TM_VU) {
                Bh = zm ? g_As_h : g_ATs_h; Bl = zm ? g_As_l : g_ATs_l;
            } else if constexpr (TMODE == TM_P) {
                if (ch < 8) { Bh = g_M2s_h; Bl = g_M2s_l; }
                else        { Bh = g_W3s_h; Bl = g_W3s_l; ldb = ND; kb = 0; }
            } else { Bh = g_W2s_h; Bl = g_W2s_l; }
            const int row = tid >> 2;
            const int cbase = (tid & 3) * 16;
            const size_t base = (size_t)(n0 + row) * ldb + kb;
#pragma unroll
            for (int i = 0; i < 2; i++) {
                const int c = cbase + i * 8;
                uint4 vh = *(const uint4*)(Bh + base + c);
                uint4 vl = *(const uint4*)(Bl + base + c);
                uint32_t sw = sw128(row * 128 + c * 2);
                sts128(sb + OFF_BH + sw, vh);
                sts128(sb + OFF_BL + sw, vl);
            }
        }
        __syncthreads();

#pragma unroll
        for (int ks = 0; ks < 4; ks++) {
            uint32_t aH[2][4], aL[2][4];
#pragma unroll
            for (int mt = 0; mt < 2; mt++) {
                uint32_t byte = (uint32_t)(wm + mt * 16 + (lane & 15)) * 128
                              + ks * 32 + (lane >> 4) * 16;
                uint32_t sw = sw128(byte);
                ldsm_x4(aH[mt], sb + OFF_XH + sw);
                ldsm_x4(aL[mt], sb + OFF_XL + sw);
            }
            uint32_t bH[NT][2], bL[NT][2];
#pragma unroll
            for (int nt = 0; nt < NT; nt++) {
                uint32_t byte = (uint32_t)(wn + nt * 8 + (lane & 7)) * 128
                              + ks * 32 + ((lane >> 3) & 1) * 16;
                uint32_t sw = sw128(byte);
                ldsm_x2(bH[nt], sb + OFF_BH + sw);
                ldsm_x2(bL[nt], sb + OFF_BL + sw);
            }
#pragma unroll
            for (int mt = 0; mt < 2; mt++)
#pragma unroll
                for (int nt = 0; nt < NT; nt++) {
                    mma16816(acc[mt][nt], aH[mt], bH[nt]);
                    mma16816(acc[mt][nt], aH[mt], bL[nt]);
                    mma16816(acc[mt][nt], aL[mt], bH[nt]);
                }
        }
        __syncthreads();
    }

    // ---- epilogues ----
#pragma unroll
    for (int mt = 0; mt < 2; mt++)
#pragma unroll
        for (int nt = 0; nt < NT; nt++) {
            const int r0  = m0 + wm + mt * 16 + (lane >> 2);
            const int col = n0 + wn + nt * 8 + (lane & 3) * 2;
            const float* a = acc[mt][nt];
#pragma unroll
            for (int half = 0; half < 2; half++) {
                const int row = r0 + half * 8;
                const float e0 = a[half * 2], e1 = a[half * 2 + 1];
                const size_t idx = (size_t)row * NH + col;
                if constexpr (TMODE == TM_L1) {
                    float tv = pT[row];
                    float h0 = tanhf(e0 + tv * w1row[col]     + pC[col]);
                    float h1 = tanhf(e1 + tv * w1row[col + 1] + pC[col + 1]);
                    *(float2*)(g_h1 + idx) = make_float2(h0, h1);
                    store_split(g_h1s_h, g_h1s_l, idx, h0, h1);
                    float a0 = 1.f - h0 * h0, a1v = 1.f - h1 * h1;
                    store_split(g_a1s_h, g_a1s_l, idx, a0, a1v);
                    store_split(g_d1s_h, g_d1s_l, idx,
                                a0 * w1row[col], a1v * w1row[col + 1]);
                } else if constexpr (TMODE == TM_H2) {
                    if (zm == 0) {
                        float h0 = tanhf(e0 + pC[col]);
                        float h1 = tanhf(e1 + pC[col + 1]);
                        *(float2*)(g_h2 + idx) = make_float2(h0, h1);
                        store_split(g_h2s_h, g_h2s_l, idx, h0, h1);
                        store_split(g_a2s_h, g_a2s_l, idx,
                                    1.f - h0 * h0, 1.f - h1 * h1);
                    } else {
                        *(float2*)(g_r2 + idx) = make_float2(e0, e1);
                    }
                } else if constexpr (TMODE == TM_VU) {
                    float* o = zm ? g_U : g_V;
                    *(float2*)(o + idx) = make_float2(e0, e1);
                } else if constexpr (TMODE == TM_P) {
                    float P0 = e0 + 2.f * g_q[col];
                    float P1 = e1 + 2.f * g_q[col + 1];
                    float2 h = *(const float2*)(g_h2 + idx);
                    float2 v = *(const float2*)(g_V + idx);
                    float w0 = (1.f - h.x * h.x) * (P0 - 2.f * h.x * v.x);
                    float w1 = (1.f - h.y * h.y) * (P1 - 2.f * h.y * v.y);
                    store_split(g_wbs_h, g_wbs_l, idx, w0, w1);
                } else {  // TM_QW
                    *(float2*)(g_r1 + idx) = make_float2(e0, e1);
                }
            }
        }
}

// ---------------- s_t reduction: s_t[b] = sum (1-h2^2)*z2*w3s ----------------
__global__ void __launch_bounds__(256)
st_red() {
    __shared__ float sh[8];
    const int tid = threadIdx.x;
    const int row = blockIdx.x * 2 + (tid >> 7);
    const int j   = (tid & 127) * 4;
    const size_t idx = (size_t)row * NH + j;
    float4 h = *(const float4*)(g_h2 + idx);
    float4 z = *(const float4*)(g_r2 + idx);
    float4 w = *(const float4*)(g_w3s + j);
    float p = (1.f - h.x*h.x) * z.x * w.x + (1.f - h.y*h.y) * z.y * w.y
            + (1.f - h.z*h.z) * z.z * w.z + (1.f - h.w*h.w) * z.w * w.w;
#pragma unroll
    for (int o = 16; o; o >>= 1) p += __shfl_xor_sync(0xffffffffu, p, o);
    if ((tid & 31) == 0) sh[tid >> 5] = p;
    __syncthreads();
    if (tid < 2)
        g_st[blockIdx.x * 2 + tid] =
            sh[tid*4] + sh[tid*4+1] + sh[tid*4+2] + sh[tid*4+3];
}

// ---------------- thin loss partial GEMMs (z=0: c@W1x, z=1: h2@W3) ------------
__global__ void __launch_bounds__(256)
loss_thin(const float* __restrict__ pW3) {
    constexpr int BK = 32;
    __shared__ __align__(16) float Xs[BK][17];
    __shared__ __align__(16) float Bs[BK][68];
    const int tid = threadIdx.x;
    const int tx = tid & 15, ty = tid >> 4;
    const int m0 = blockIdx.y * 16;
    const int z  = blockIdx.z;
    const float* Bg = z ? pW3 : g_W1T;

    float acc[4] = {0.f, 0.f, 0.f, 0.f};
    for (int k0 = 0; k0 < NH; k0 += BK) {
        {
            int row = tid >> 4;
            int kc  = (tid & 15) * 2;
            size_t idx = (size_t)(m0 + row) * NH + k0 + kc;
            if (z) {
                float2 v = *(const float2*)(g_h2 + idx);
                Xs[kc][row] = v.x; Xs[kc + 1][row] = v.y;
            } else {
                float2 q = *(const float2*)(g_r1 + idx);
                float2 h = *(const float2*)(g_h1 + idx);
                float2 u = *(const float2*)(g_U + idx);
                float a0 = 1.f - h.x * h.x, a1v = 1.f - h.y * h.y;
                Xs[kc][row]     = a0  * (q.x - 2.f * h.x * u.x);
                Xs[kc + 1][row] = a1v * (q.y - 2.f * h.y * u.y);
            }
        }
        {
            int brow = tid >> 4, bnq = (tid & 15) * 4;
            *(float4*)&Bs[brow][bnq] =
                *(const float4*)(Bg + (size_t)(k0 + brow) * ND + bnq);
            *(float4*)&Bs[brow + 16][bnq] =
                *(const float4*)(Bg + (size_t)(k0 + brow + 16) * ND + bnq);
        }
        __syncthreads();
#pragma unroll
        for (int kk = 0; kk < BK; kk++) {
            float a = Xs[kk][ty];
            float4 b = *(const float4*)&Bs[kk][tx * 4];
            acc[0] += a * b.x; acc[1] += a * b.y;
            acc[2] += a * b.z; acc[3] += a * b.w;
        }
        __syncthreads();
    }
    float* o = (z ? g_Gp2 : g_Gp1) + (size_t)(m0 + ty) * ND + tx * 4;
    *(float4*)o = make_float4(acc[0], acc[1], acc[2], acc[3]);
}

// ---------------- final loss reduce ------------------------------------------
__global__ void __launch_bounds__(256)
loss_red(const float* __restrict__ beta, const float* __restrict__ b3,
         float* __restrict__ out) {
    __shared__ float sh[8];
    const int tid = threadIdx.x;
    const int row = blockIdx.x * 4 + (tid >> 6);
    const int i   = tid & 63;
    const size_t idx = (size_t)row * ND + i;
    float g = g_Gp1[idx] + g_Gp2[idx] + b3[i];
    float v = fabsf(g_st[row] - 0.5f * beta[row] * g);
#pragma unroll
    for (int o = 16; o; o >>= 1) v += __shfl_xor_sync(0xffffffffu, v, o);
    if ((tid & 31) == 0) sh[tid >> 5] = v;
    __syncthreads();
    if (tid < 4)
        out[blockIdx.x * 4 + tid] = (sh[tid*2] + sh[tid*2+1]) * (1.f / 64.f);
}

// ---------------- launch -----------------------------------------------------
#define SM64  (2 * 64 * 128 + 16384)    // 32 KB
#define SM128 (2 * 128 * 128 + 16384)   // 48 KB

extern "C" void kernel_launch(void* const* d_in, const int* in_sizes, int n_in,
                              void* d_out, int out_size) {
    const float* x    = (const float*)d_in[0];
    const float* t    = (const float*)d_in[1];
    const float* beta = (const float*)d_in[2];
    const float* W1   = (const float*)d_in[3];
    const float* b1   = (const float*)d_in[4];
    const float* W2   = (const float*)d_in[5];
    const float* b2   = (const float*)d_in[6];
    const float* W3   = (const float*)d_in[7];
    const float* b3   = (const float*)d_in[8];
    float* out = (float*)d_out;
    const float* w1t = W1 + (size_t)ND * NH;   // W1 t-row

    cudaFuncSetAttribute(tmma<TM_L1, 64>,  cudaFuncAttributeMaxDynamicSharedMemorySize, SM64);
    cudaFuncSetAttribute(tmma<TM_H2, 128>, cudaFuncAttributeMaxDynamicSharedMemorySize, SM128);
    cudaFuncSetAttribute(tmma<TM_VU, 128>, cudaFuncAttributeMaxDynamicSharedMemorySize, SM128);
    cudaFuncSetAttribute(tmma<TM_P, 64>,   cudaFuncAttributeMaxDynamicSharedMemorySize, SM64);
    cudaFuncSetAttribute(tmma<TM_QW, 64>,  cudaFuncAttributeMaxDynamicSharedMemorySize, SM64);

    dim3 gT64 (NH/64, NB/64,  1);   // 128 blocks
    dim3 gT128(NH/64, NB/128, 2);   // 128 blocks

    prep_kernel<<<dim3(NH/16, NH/16), dim3(16,16)>>>(W1, W2, W3, b3);
    // h1 = tanh([x,t]@W1 + b1); writes h1, h1s, a1s, d1s
    tmma<TM_L1, 64><<<gT64, 256, SM64>>>(x, b1, t, w1t);
    // z0: h2 = tanh(h1@W2 + b2) (+h2s,a2s); z1: z2 = d1@W2
    tmma<TM_H2, 128><<<gT128, 256, SM128>>>(nullptr, b2, nullptr, nullptr);
    // s_t
    st_red<<<NB/2, 256>>>();
    // z0: V = a1@A; z1: U = a2@A^T
    tmma<TM_VU, 128><<<gT128, 256, SM128>>>(nullptr, nullptr, nullptr, nullptr);
    // P = 2 h2@M + x@W3^T + 2q; wb = a2*(P - 2 h2 V)  (K=576)
    tmma<TM_P, 64><<<gT64, 256, SM64>>>(x, nullptr, nullptr, nullptr);
    // qw = wb @ W2^T
    tmma<TM_QW, 64><<<gT64, 256, SM64>>>(nullptr, nullptr, nullptr, nullptr);
    // Gp1 = c@W1x^T (c on the fly), Gp2 = h2@W3
    loss_thin<<<dim3(1, NB/16, 2), 256>>>(W3);
    // loss = mean |s_t - 0.5 beta (Gp1+Gp2+b3)|
    loss_red<<<NB/4, 256>>>(beta, b3, out);
}

// round 6
// speedup vs baseline: 1.0149x; 1.0149x over previous
#include <cuda_runtime.h>
#include <cuda_bf16.h>
#include <math.h>
#include <stdint.h>

#define NB 1024
#define ND 64
#define NH 512

typedef __nv_bfloat16 bf16;

// ---------------- fp32 scratch ----------------
__device__ __align__(256) float g_A  [NH*NH];   // A[k,l] = W2[k,l]*(W3 W1x^T)[l,k]
__device__ __align__(256) float g_AT [NH*NH];
__device__ __align__(256) float g_W2T[NH*NH];   // [l,k] = W2[k,l]
__device__ __align__(256) float g_M2 [NH*NH];   // 2*(W3 W3^T)
__device__ __align__(256) float g_W1T[NH*ND];   // [k,i] = W1[i,k] (x-rows)
__device__ __align__(256) float g_w3s[NH];
__device__ __align__(256) float g_q  [NH];      // q[n] = b3 . W3[n,:]
__device__ __align__(256) float g_h1 [NB*NH];
__device__ __align__(256) float g_h2 [NB*NH];
__device__ __align__(256) float g_U  [NB*NH];
__device__ __align__(256) float g_V  [NB*NH];
__device__ __align__(256) float g_wb [NB*NH];
__device__ __align__(256) float g_r1 [NB*NH];   // h2raw -> later qw
__device__ __align__(256) float g_r2 [NB*NH];   // z2
__device__ __align__(256) float g_st [NB];
__device__ __align__(256) float g_Gp1[NB*ND];
__device__ __align__(256) float g_Gp2[NB*ND];

// ---------------- helpers ----------------
__device__ __forceinline__ uint32_t smem_u32(const void* p) {
    return (uint32_t)__cvta_generic_to_shared(p);
}
__device__ __forceinline__ void sts_v2(uint32_t addr, uint32_t a, uint32_t b) {
    asm volatile("st.shared.v2.b32 [%0], {%1,%2};" :: "r"(addr), "r"(a), "r"(b));
}
__device__ __forceinline__ void split2(float x0, float x1, uint32_t& hi, uint32_t& lo) {
    bf16 h0 = __float2bfloat16(x0), h1 = __float2bfloat16(x1);
    bf16 l0 = __float2bfloat16(x0 - __bfloat162float(h0));
    bf16 l1 = __float2bfloat16(x1 - __bfloat162float(h1));
    __nv_bfloat162 H; H.x = h0; H.y = h1;
    __nv_bfloat162 L; L.x = l0; L.y = l1;
    hi = *reinterpret_cast<uint32_t*>(&H);
    lo = *reinterpret_cast<uint32_t*>(&L);
}
__device__ __forceinline__ void ldsm_x4(uint32_t* r, uint32_t addr) {
    asm volatile("ldmatrix.sync.aligned.m8n8.x4.shared.b16 {%0,%1,%2,%3}, [%4];"
                 : "=r"(r[0]), "=r"(r[1]), "=r"(r[2]), "=r"(r[3]) : "r"(addr));
}
__device__ __forceinline__ void ldsm_x2(uint32_t* r, uint32_t addr) {
    asm volatile("ldmatrix.sync.aligned.m8n8.x2.shared.b16 {%0,%1}, [%2];"
                 : "=r"(r[0]), "=r"(r[1]) : "r"(addr));
}
__device__ __forceinline__ void mma16816(float* c, const uint32_t* a, const uint32_t* b) {
    asm volatile(
        "mma.sync.aligned.m16n8k16.row.col.f32.bf16.bf16.f32 "
        "{%0,%1,%2,%3}, {%4,%5,%6,%7}, {%8,%9}, {%0,%1,%2,%3};"
        : "+f"(c[0]), "+f"(c[1]), "+f"(c[2]), "+f"(c[3])
        : "r"(a[0]), "r"(a[1]), "r"(a[2]), "r"(a[3]), "r"(b[0]), "r"(b[1]));
}
__device__ __forceinline__ uint32_t sw128(uint32_t byte) {
    return byte ^ ((byte >> 3) & 0x70);
}

// ---------------- prep (fp32 only) -------------------------------------------
__global__ void prep_kernel(const float* __restrict__ W1,
                            const float* __restrict__ W2,
                            const float* __restrict__ W3,
                            const float* __restrict__ b3) {
    int k = blockIdx.x * 16 + threadIdx.x;
    int l = blockIdx.y * 16 + threadIdx.y;
    float c = 0.f, mv = 0.f;
#pragma unroll
    for (int i = 0; i < ND; i++) {
        c  += W3[l*ND + i] * W1[i*NH + k];
        mv += W3[k*ND + i] * W3[l*ND + i];
    }
    float w2 = W2[k*NH + l];
    float a  = w2 * c;
    g_A  [(size_t)k*NH + l] = a;
    g_AT [(size_t)l*NH + k] = a;
    g_W2T[(size_t)l*NH + k] = w2;
    g_M2 [(size_t)k*NH + l] = 2.f * mv;
    if (l < ND) g_W1T[k*ND + l] = W1[l*NH + k];
    if (k == 0 && blockIdx.x == 0) {
        float s1 = 0.f, s2 = 0.f;
#pragma unroll
        for (int j = 0; j < ND; j++) {
            s1 += W3[l*ND + j];
            s2 += b3[j] * W3[l*ND + j];
        }
        g_w3s[l] = s1;
        g_q[l]   = s2;
    }
}

// ---------------- tensor GEMMs (inline fp32->bf16 hi/lo, prefetch pipeline) ---
enum { TM_L1 = 0, TM_H2 = 1, TM_VU = 2, TM_P = 3, TM_QW = 4 };

template<int TMODE, int BM>
__global__ void __launch_bounds__(256, 1)
tmma(const float* __restrict__ pX, const float* __restrict__ pB,
     const float* __restrict__ pC, const float* __restrict__ pT,
     const float* __restrict__ w1row) {
    extern __shared__ __align__(1024) char tsm[];
    const uint32_t sb = smem_u32(tsm);
    constexpr int XSZ = BM * 128;
    constexpr uint32_t OFF_XH = 0, OFF_XL = XSZ;
    constexpr uint32_t OFF_BH = 2 * XSZ, OFF_BL = 2 * XSZ + 8192;
    constexpr int NT = (BM == 128) ? 4 : 2;
    constexpr int NF4 = (BM == 128) ? 8 : 4;
    constexpr int NCHUNK = (TMODE == TM_L1) ? 1 : (TMODE == TM_P) ? 9 : 8;

    const int tid  = threadIdx.x;
    const int lane = tid & 31, wid = tid >> 5;
    const int zm = blockIdx.z;
    const int n0 = blockIdx.x * 64;
    const int m0 = blockIdx.y * BM;
    const int wm = (BM == 128 ? (wid & 3) : (wid & 1)) * 32;
    const int wn = (BM == 128 ? (wid >> 2) * 32 : (wid >> 1) * 16);

    const int xrow = (BM == 128) ? (tid >> 1) : (tid >> 2);
    const int xcb  = (BM == 128) ? ((tid & 1) * 32) : ((tid & 3) * 16);
    const int brow = tid >> 2;
    const int bcb  = (tid & 3) * 16;

    float4 xreg[NF4], breg[4];

    auto ldX = [&](int ch) {
        const float* src; int lda = NH, k0 = ch * 64;
        if constexpr (TMODE == TM_L1)      { src = pX; lda = 64; k0 = 0; }
        else if constexpr (TMODE == TM_H2)   src = g_h1;
        else if constexpr (TMODE == TM_VU)   src = zm ? g_h2 : g_h1;
        else if constexpr (TMODE == TM_P) {
            if (ch == 8) { src = pX; lda = 64; k0 = 0; } else src = g_h2;
        } else                               src = g_wb;
        const float* xr = src + (size_t)(m0 + xrow) * lda + k0 + xcb;
#pragma unroll
        for (int i = 0; i < NF4; i++) xreg[i] = *(const float4*)(xr + i * 4);
    };
    auto ldB = [&](int ch) {
        const float* src; int ldb = NH, k0 = ch * 64;
        if constexpr (TMODE == TM_L1)      { src = g_W1T; ldb = ND; k0 = 0; }
        else if constexpr (TMODE == TM_H2)   src = g_W2T;
        else if constexpr (TMODE == TM_VU)   src = zm ? g_A : g_AT;
        else if constexpr (TMODE == TM_P) {
            if (ch == 8) { src = pB; ldb = ND; k0 = 0; } else src = g_M2;
        } else                               src = pB;      // QW: W2
        const float* br = src + (size_t)(n0 + brow) * ldb + k0 + bcb;
#pragma unroll
        for (int i = 0; i < 4; i++) breg[i] = *(const float4*)(br + i * 4);
    };
    auto stX = [&](int ch) {
#pragma unroll
        for (int i = 0; i < NF4; i++) {
            float4 v = xreg[i];
            const int col = xcb + i * 4;
            if constexpr (TMODE == TM_H2) {
                if (zm) {   // d1 = (1-h1^2)*w1t[k]
                    float4 w = *(const float4*)(w1row + ch * 64 + col);
                    v.x = (1.f - v.x*v.x) * w.x; v.y = (1.f - v.y*v.y) * w.y;
                    v.z = (1.f - v.z*v.z) * w.z; v.w = (1.f - v.w*v.w) * w.w;
                }
            } else if constexpr (TMODE == TM_VU) {
                v.x = 1.f - v.x*v.x; v.y = 1.f - v.y*v.y;
                v.z = 1.f - v.z*v.z; v.w = 1.f - v.w*v.w;
            }
            uint32_t h01, l01, h23, l23;
            split2(v.x, v.y, h01, l01);
            split2(v.z, v.w, h23, l23);
            uint32_t sw = sw128(xrow * 128 + col * 2);
            sts_v2(sb + OFF_XH + sw, h01, h23);
            sts_v2(sb + OFF_XL + sw, l01, l23);
        }
    };
    auto stB = [&]() {
#pragma unroll
        for (int i = 0; i < 4; i++) {
            float4 v = breg[i];
            const int col = bcb + i * 4;
            uint32_t h01, l01, h23, l23;
            split2(v.x, v.y, h01, l01);
            split2(v.z, v.w, h23, l23);
            uint32_t sw = sw128(brow * 128 + col * 2);
            sts_v2(sb + OFF_BH + sw, h01, h23);
            sts_v2(sb + OFF_BL + sw, l01, l23);
        }
    };

    float acc[2][NT][4];
#pragma unroll
    for (int mt = 0; mt < 2; mt++)
#pragma unroll
        for (int nt = 0; nt < NT; nt++)
#pragma unroll
            for (int i = 0; i < 4; i++) acc[mt][nt][i] = 0.f;

    ldX(0); ldB(0);
    for (int ch = 0; ch < NCHUNK; ch++) {
        stX(ch); stB();
        __syncthreads();
        if (ch + 1 < NCHUNK) { ldX(ch + 1); ldB(ch + 1); }  // overlap with MMA

#pragma unroll
        for (int ks = 0; ks < 4; ks++) {
            uint32_t aH[2][4], aL[2][4];
#pragma unroll
            for (int mt = 0; mt < 2; mt++) {
                uint32_t byte = (uint32_t)(wm + mt * 16 + (lane & 15)) * 128
                              + ks * 32 + (lane >> 4) * 16;
                uint32_t sw = sw128(byte);
                ldsm_x4(aH[mt], sb + OFF_XH + sw);
                ldsm_x4(aL[mt], sb + OFF_XL + sw);
            }
            uint32_t bH[NT][2], bL[NT][2];
#pragma unroll
            for (int nt = 0; nt < NT; nt++) {
                uint32_t byte = (uint32_t)(wn + nt * 8 + (lane & 7)) * 128
                              + ks * 32 + ((lane >> 3) & 1) * 16;
                uint32_t sw = sw128(byte);
                ldsm_x2(bH[nt], sb + OFF_BH + sw);
                ldsm_x2(bL[nt], sb + OFF_BL + sw);
            }
#pragma unroll
            for (int mt = 0; mt < 2; mt++)
#pragma unroll
                for (int nt = 0; nt < NT; nt++) {
                    mma16816(acc[mt][nt], aH[mt], bH[nt]);
                    mma16816(acc[mt][nt], aH[mt], bL[nt]);
                    mma16816(acc[mt][nt], aL[mt], bH[nt]);
                }
        }
        __syncthreads();
    }

    // ---- epilogues (fp32 outputs only) ----
#pragma unroll
    for (int mt = 0; mt < 2; mt++)
#pragma unroll
        for (int nt = 0; nt < NT; nt++) {
            const int r0  = m0 + wm + mt * 16 + (lane >> 2);
            const int col = n0 + wn + nt * 8 + (lane & 3) * 2;
            const float* a = acc[mt][nt];
#pragma unroll
            for (int half = 0; half < 2; half++) {
                const int row = r0 + half * 8;
                const float e0 = a[half * 2], e1 = a[half * 2 + 1];
                const size_t idx = (size_t)row * NH + col;
                if constexpr (TMODE == TM_L1) {
                    float tv = pT[row];
                    float h0 = tanhf(e0 + tv * w1row[col]     + pC[col]);
                    float h1 = tanhf(e1 + tv * w1row[col + 1] + pC[col + 1]);
                    *(float2*)(g_h1 + idx) = make_float2(h0, h1);
                } else if constexpr (TMODE == TM_H2) {
                    float* o = zm ? g_r2 : g_r1;
                    *(float2*)(o + idx) = make_float2(e0, e1);
                } else if constexpr (TMODE == TM_VU) {
                    float* o = zm ? g_U : g_V;
                    *(float2*)(o + idx) = make_float2(e0, e1);
                } else if constexpr (TMODE == TM_P) {
                    float P0 = e0 + 2.f * g_q[col];
                    float P1 = e1 + 2.f * g_q[col + 1];
                    float2 h = *(const float2*)(g_h2 + idx);
                    float2 v = *(const float2*)(g_V + idx);
                    float w0 = (1.f - h.x * h.x) * (P0 - 2.f * h.x * v.x);
                    float w1 = (1.f - h.y * h.y) * (P1 - 2.f * h.y * v.y);
                    *(float2*)(g_wb + idx) = make_float2(w0, w1);
                } else {  // TM_QW
                    *(float2*)(g_r1 + idx) = make_float2(e0, e1);
                }
            }
        }
}

// ---------------- st_red: h2 = tanh(r1+b2); s_t = sum (1-h2^2)*z2*w3s ---------
__global__ void __launch_bounds__(256)
st_red(const float* __restrict__ b2) {
    __shared__ float sh[8];
    const int tid = threadIdx.x;
    const int row = blockIdx.x * 4 + (tid >> 6);
    const int j   = (tid & 63) * 8;
    const size_t idx = (size_t)row * NH + j;
    float4 ra = *(const float4*)(g_r1 + idx);
    float4 rb = *(const float4*)(g_r1 + idx + 4);
    float4 za = *(const float4*)(g_r2 + idx);
    float4 zb = *(const float4*)(g_r2 + idx + 4);
    float4 wa = *(const float4*)(g_w3s + j);
    float4 wb = *(const float4*)(g_w3s + j + 4);
    float4 ba = *(const float4*)(b2 + j);
    float4 bb = *(const float4*)(b2 + j + 4);
    float4 ha = make_float4(tanhf(ra.x + ba.x), tanhf(ra.y + ba.y),
                            tanhf(ra.z + ba.z), tanhf(ra.w + ba.w));
    float4 hb = make_float4(tanhf(rb.x + bb.x), tanhf(rb.y + bb.y),
                            tanhf(rb.z + bb.z), tanhf(rb.w + bb.w));
    *(float4*)(g_h2 + idx)     = ha;
    *(float4*)(g_h2 + idx + 4) = hb;
    float p = (1.f - ha.x*ha.x) * za.x * wa.x + (1.f - ha.y*ha.y) * za.y * wa.y
            + (1.f - ha.z*ha.z) * za.z * wa.z + (1.f - ha.w*ha.w) * za.w * wa.w
            + (1.f - hb.x*hb.x) * zb.x * wb.x + (1.f - hb.y*hb.y) * zb.y * wb.y
            + (1.f - hb.z*hb.z) * zb.z * wb.z + (1.f - hb.w*hb.w) * zb.w * wb.w;
#pragma unroll
    for (int o = 16; o; o >>= 1) p += __shfl_xor_sync(0xffffffffu, p, o);
    if ((tid & 31) == 0) sh[tid >> 5] = p;
    __syncthreads();
    if (tid < 4)
        g_st[blockIdx.x * 4 + tid] = sh[tid * 2] + sh[tid * 2 + 1];
}

// ---------------- thin loss partial GEMMs (z=0: c@W1x^T, z=1: h2@W3) ----------
__global__ void __launch_bounds__(256)
loss_thin(const float* __restrict__ pW3) {
    constexpr int BK = 32;
    __shared__ __align__(16) float Xs[BK][17];
    __shared__ __align__(16) float Bs[BK][68];
    const int tid = threadIdx.x;
    const int tx = tid & 15, ty = tid >> 4;
    const int m0 = blockIdx.y * 16;
    const int z  = blockIdx.z;
    const float* Bg = z ? pW3 : g_W1T;

    float acc[4] = {0.f, 0.f, 0.f, 0.f};
    for (int k0 = 0; k0 < NH; k0 += BK) {
        {
            int row = tid >> 4;
            int kc  = (tid & 15) * 2;
            size_t idx = (size_t)(m0 + row) * NH + k0 + kc;
            if (z) {
                float2 v = *(const float2*)(g_h2 + idx);
                Xs[kc][row] = v.x; Xs[kc + 1][row] = v.y;
            } else {
                float2 q = *(const float2*)(g_r1 + idx);
                float2 h = *(const float2*)(g_h1 + idx);
                float2 u = *(const float2*)(g_U + idx);
                float a0 = 1.f - h.x * h.x, a1v = 1.f - h.y * h.y;
                Xs[kc][row]     = a0  * (q.x - 2.f * h.x * u.x);
                Xs[kc + 1][row] = a1v * (q.y - 2.f * h.y * u.y);
            }
        }
        {
            int brow = tid >> 4, bnq = (tid & 15) * 4;
            *(float4*)&Bs[brow][bnq] =
                *(const float4*)(Bg + (size_t)(k0 + brow) * ND + bnq);
            *(float4*)&Bs[brow + 16][bnq] =
                *(const float4*)(Bg + (size_t)(k0 + brow + 16) * ND + bnq);
        }
        __syncthreads();
#pragma unroll
        for (int kk = 0; kk < BK; kk++) {
            float a = Xs[kk][ty];
            float4 b = *(const float4*)&Bs[kk][tx * 4];
            acc[0] += a * b.x; acc[1] += a * b.y;
            acc[2] += a * b.z; acc[3] += a * b.w;
        }
        __syncthreads();
    }
    float* o = (z ? g_Gp2 : g_Gp1) + (size_t)(m0 + ty) * ND + tx * 4;
    *(float4*)o = make_float4(acc[0], acc[1], acc[2], acc[3]);
}

// ---------------- final loss reduce ------------------------------------------
__global__ void __launch_bounds__(256)
loss_red(const float* __restrict__ beta, const float* __restrict__ b3,
         float* __restrict__ out) {
    __shared__ float sh[8];
    const int tid = threadIdx.x;
    const int row = blockIdx.x * 4 + (tid >> 6);
    const int i   = tid & 63;
    const size_t idx = (size_t)row * ND + i;
    float g = g_Gp1[idx] + g_Gp2[idx] + b3[i];
    float v = fabsf(g_st[row] - 0.5f * beta[row] * g);
#pragma unroll
    for (int o = 16; o; o >>= 1) v += __shfl_xor_sync(0xffffffffu, v, o);
    if ((tid & 31) == 0) sh[tid >> 5] = v;
    __syncthreads();
    if (tid < 4)
        out[blockIdx.x * 4 + tid] = (sh[tid*2] + sh[tid*2+1]) * (1.f / 64.f);
}

// ---------------- launch -----------------------------------------------------
#define SM64  (2 * 64 * 128 + 16384)    // 32 KB
#define SM128 (2 * 128 * 128 + 16384)   // 48 KB

extern "C" void kernel_launch(void* const* d_in, const int* in_sizes, int n_in,
                              void* d_out, int out_size) {
    const float* x    = (const float*)d_in[0];
    const float* t    = (const float*)d_in[1];
    const float* beta = (const float*)d_in[2];
    const float* W1   = (const float*)d_in[3];
    const float* b1   = (const float*)d_in[4];
    const float* W2   = (const float*)d_in[5];
    const float* b2   = (const float*)d_in[6];
    const float* W3   = (const float*)d_in[7];
    const float* b3   = (const float*)d_in[8];
    float* out = (float*)d_out;
    const float* w1t = W1 + (size_t)ND * NH;   // W1 t-row

    cudaFuncSetAttribute(tmma<TM_L1, 64>,  cudaFuncAttributeMaxDynamicSharedMemorySize, SM64);
    cudaFuncSetAttribute(tmma<TM_H2, 128>, cudaFuncAttributeMaxDynamicSharedMemorySize, SM128);
    cudaFuncSetAttribute(tmma<TM_VU, 128>, cudaFuncAttributeMaxDynamicSharedMemorySize, SM128);
    cudaFuncSetAttribute(tmma<TM_P, 64>,   cudaFuncAttributeMaxDynamicSharedMemorySize, SM64);
    cudaFuncSetAttribute(tmma<TM_QW, 64>,  cudaFuncAttributeMaxDynamicSharedMemorySize, SM64);

    dim3 gT64 (NH/64, NB/64,  1);   // 128 blocks
    dim3 gT128(NH/64, NB/128, 2);   // 128 blocks

    prep_kernel<<<dim3(NH/16, NH/16), dim3(16,16)>>>(W1, W2, W3, b3);
    // h1 = tanh([x,t]@W1 + b1)
    tmma<TM_L1, 64><<<gT64, 256, SM64>>>(x, nullptr, b1, t, w1t);
    // z0: h2raw = h1@W2; z1: z2 = d1@W2
    tmma<TM_H2, 128><<<gT128, 256, SM128>>>(nullptr, nullptr, nullptr, nullptr, w1t);
    // h2 = tanh(h2raw + b2); s_t
    st_red<<<NB/4, 256>>>(b2);
    // z0: V = a1@A; z1: U = a2@A^T
    tmma<TM_VU, 128><<<gT128, 256, SM128>>>(nullptr, nullptr, nullptr, nullptr, nullptr);
    // P = h2@(2 W3W3^T) + x@W3^T + 2q; wb = a2*(P - 2 h2 V)   (K=576)
    tmma<TM_P, 64><<<gT64, 256, SM64>>>(x, W3, nullptr, nullptr, nullptr);
    // qw = wb @ W2^T
    tmma<TM_QW, 64><<<gT64, 256, SM64>>>(nullptr, W2, nullptr, nullptr, nullptr);
    // Gp1 = c@W1x^T (c on the fly), Gp2 = h2@W3
    loss_thin<<<dim3(1, NB/16, 2), 256>>>(W3);
    // loss = mean |s_t - 0.5 beta (Gp1+Gp2+b3)|
    loss_red<<<NB/4, 256>>>(beta, b3, out);
}